// round 12
// baseline (speedup 1.0000x reference)
#include <cuda_runtime.h>
#include <math.h>

#define Bn 2
#define Cn 21
#define Hn 512
#define Wn 512
#define HL 128
#define WL 128
#define Kn 11
#define SPANn 5
#define KKn 121

#define PP 144
#define XOFF 5
#define YOFF 8
#define PLANE (PP*PP)

#define GK_TILE 128
#define GK_SMEM_BYTES (KKn * GK_TILE * 4)

__device__ float g_ppad [Bn*Cn*PLANE];
__device__ float g_msg  [Bn*Cn*HL*WL];
__device__ float g_cf   [Bn*3*HL*WL];

__constant__ float c_wtab[4] = {0.375f, 0.125f, 0.875f, 0.625f};

// ---------------------------------------------------------------------------
__global__ void k_zero() {
    int idx = blockIdx.x * 256 + threadIdx.x;
    if (idx < Bn*Cn*PLANE/4) ((float4*)g_ppad)[idx] = make_float4(0.f,0.f,0.f,0.f);
}

// ---------------------------------------------------------------------------
__global__ void k_pool_img(const float* __restrict__ img, const float* __restrict__ schan) {
    int idx = blockIdx.x * 256 + threadIdx.x;
    if (idx >= Bn*3*HL*WL) return;
    int y = idx & (WL-1);
    int x = (idx >> 7) & (HL-1);
    int c = (idx >> 14) % 3;
    int b = idx / (3*HL*WL);
    const float* src = img + ((b*3 + c)*Hn + x*4)*Wn + y*4;
    float s = 0.f;
    #pragma unroll
    for (int i = 0; i < 4; i++)
        #pragma unroll
        for (int j = 0; j < 4; j++) s += src[i*Wn + j];
    g_cf[idx] = s * (schan[0] * 0.0625f);
}

// ---------------------------------------------------------------------------
// 3) pooled init pred, ONE row per thread (exact R11)
__global__ __launch_bounds__(256) void k_init(const float* __restrict__ unary) {
    __shared__ float part[8*8*Cn];       // [w][yq][c]
    int b = blockIdx.z;
    int w = threadIdx.x >> 5, l = threadIdx.x & 31;
    int X = blockIdx.y*8 + w;
    int Y = blockIdx.x*32 + l;
    const float* up = unary + ((size_t)(b*Cn)*Hn + X)*Wn + Y;
    float u[Cn];
    float m = -1e30f;
    #pragma unroll
    for (int c = 0; c < Cn; c++) {
        u[c] = __ldg(up + (size_t)c*Hn*Wn);
        m = fmaxf(m, u[c]);
    }
    float s = 0.f;
    #pragma unroll
    for (int c = 0; c < Cn; c++) s += __expf(u[c] - m);
    float lse = m + __logf(s);
    int yq = l >> 2;
    #pragma unroll
    for (int c = 0; c < Cn; c++) {
        float r = u[c] - lse;
        r += __shfl_xor_sync(0xffffffffu, r, 1);
        r += __shfl_xor_sync(0xffffffffu, r, 2);
        if ((l & 3) == 0) part[(w*8 + yq)*Cn + c] = r;
    }
    __syncthreads();
    for (int idx = threadIdx.x; idx < 2*8*Cn; idx += 256) {
        int c = idx % Cn, rem = idx / Cn;
        int q = rem & 7, xc = rem >> 3;
        float ss = part[((xc*4+0)*8 + q)*Cn + c] + part[((xc*4+1)*8 + q)*Cn + c]
                 + part[((xc*4+2)*8 + q)*Cn + c] + part[((xc*4+3)*8 + q)*Cn + c];
        g_ppad[((size_t)(b*Cn + c)*PP + blockIdx.y*2 + xc + XOFF)*PP
               + blockIdx.x*8 + q + YOFF] = ss * 0.0625f;
    }
}

// ---------------------------------------------------------------------------
// 4) message passing with IN-KERNEL gauss computation.
//    Stage cf tile -> compute gk[121][128] in smem -> R9 stencil consume loop.
__global__ __launch_bounds__(224) void k_msg(const float* __restrict__ pos_sdims,
                                             const float* __restrict__ pos_compat,
                                             const float* __restrict__ col_compat) {
    extern __shared__ float gk_s[];           // [121][128]
    __shared__ float cf_s[3][18*26];
    __shared__ float pos_s[KKn];
    const int t = threadIdx.x;
    const int b = blockIdx.z;
    const int tyi = blockIdx.x, txi = blockIdx.y;

    // --- stage cf halo + pos table ---
    int x0 = txi*8 - SPANn, y0 = tyi*16 - SPANn;
    if (t < KKn) {
        int i = t / 11, j = t - i*11;
        int dx = i - SPANn, dy = j - SPANn;
        float sd4 = 4.f * pos_sdims[0];
        float dpos2 = sd4*sd4 * (float)(dx*dx + dy*dy);
        pos_s[t] = pos_compat[0] * __expf(-0.5f*dpos2);
    }
    for (int i2 = t; i2 < 3*468; i2 += 224) {
        int c = i2 / 468, rem = i2 % 468;
        int xx = x0 + rem/26, yy = y0 + rem%26;
        float v = 0.f;
        if ((unsigned)xx < HL && (unsigned)yy < WL)
            v = g_cf[((b*3 + c)*HL + xx)*WL + yy];
        cf_s[c][rem] = v;
    }
    __syncthreads();

    // --- compute gk tile in smem ---
    {
        float cc = col_compat[0];
        #pragma unroll 4
        for (int idx = t; idx < KKn*GK_TILE; idx += 224) {
            int ij = idx >> 7, pix = idx & 127;
            int i = ij / 11, j = ij - i*11;
            int px = pix >> 4, py = pix & 15;
            int gx = txi*8 + px, gy = tyi*16 + py;
            bool valid = ((unsigned)(gx + i - SPANn) < HL) &&
                         ((unsigned)(gy + j - SPANn) < WL);
            int ctr = (px + SPANn)*26 + (py + SPANn);
            int si  = (px + i)*26 + (py + j);
            float d0 = cf_s[0][si] - cf_s[0][ctr];
            float d1 = cf_s[1][si] - cf_s[1][ctr];
            float d2 = cf_s[2][si] - cf_s[2][ctr];
            float dcol2 = d0*d0 + d1*d1 + d2*d2;
            gk_s[idx] = valid ? (pos_s[ij] + cc * __expf(-0.5f*dcol2)) : 0.f;
        }
    }
    __syncthreads();

    // --- consume (exact R9/R11 stencil) ---
    const int chunk = t >> 5, lane = t & 31;
    const int xrow = lane >> 2, yg = lane & 3;
    const int pxg = txi*8 + xrow;
    const int Yb  = tyi*16 + yg*4;

    float acc[3][4];
    #pragma unroll
    for (int c = 0; c < 3; c++)
        #pragma unroll
        for (int k = 0; k < 4; k++) acc[c][k] = 0.f;

    const int pix = lane*4;
    #pragma unroll 1
    for (int i = 0; i < 11; i++) {
        float pr[3][20];
        #pragma unroll
        for (int c = 0; c < 3; c++) {
            const float4* pp = (const float4*)(g_ppad +
                ((size_t)(b*Cn + chunk*3 + c)*PP + (pxg + i))*PP + Yb);
            #pragma unroll
            for (int q = 0; q < 5; q++) {
                float4 v = __ldg(pp + q);
                pr[c][q*4+0] = v.x; pr[c][q*4+1] = v.y;
                pr[c][q*4+2] = v.z; pr[c][q*4+3] = v.w;
            }
        }
        const float* gs = gk_s + i*11*GK_TILE + pix;
        #pragma unroll
        for (int j = 0; j < 11; j++) {
            float4 gv = *(const float4*)(gs + j*GK_TILE);
            #pragma unroll
            for (int c = 0; c < 3; c++) {
                acc[c][0] += gv.x * pr[c][0 + j + 3];
                acc[c][1] += gv.y * pr[c][1 + j + 3];
                acc[c][2] += gv.z * pr[c][2 + j + 3];
                acc[c][3] += gv.w * pr[c][3 + j + 3];
            }
        }
    }

    #pragma unroll
    for (int c = 0; c < 3; c++) {
        float* mp = g_msg + ((size_t)(b*Cn + chunk*3 + c)*HL + pxg)*WL + Yb;
        *(float4*)mp = make_float4(acc[c][0], acc[c][1], acc[c][2], acc[c][3]);
    }
}

// ---------------------------------------------------------------------------
// 5) fused iter, ONE row per thread (exact R11)
__global__ __launch_bounds__(256) void k_iter(const float* __restrict__ unary,
                                              const float* __restrict__ weight) {
    __shared__ float m_s[Cn*40];         // [c][4 x][10 y]
    __shared__ float part[8*8*Cn];
    int b = blockIdx.z;
    int t = threadIdx.x, w = t >> 5, l = t & 31;
    int lx0 = blockIdx.y*2 - 1, ly0 = blockIdx.x*8 - 1;
    for (int i = t; i < Cn*40; i += 256) {
        int c = i / 40, rem = i % 40;
        int xx = lx0 + rem/10; xx = max(0, min(HL-1, xx));
        int yy = ly0 + rem%10; yy = max(0, min(WL-1, yy));
        m_s[i] = g_msg[((b*Cn + c)*HL + xx)*WL + yy];
    }
    __syncthreads();
    int X = blockIdx.y*8 + w;
    int Y = blockIdx.x*32 + l;
    const float* up = unary + ((size_t)(b*Cn)*Hn + X)*Wn + Y;
    float wgt = weight[0], uw = 1.f - wgt;
    int rx = w & 3, ry = l & 3;
    float wx0 = c_wtab[rx], wx1 = 1.f - wx0;
    float wy0 = c_wtab[ry], wy1 = 1.f - wy0;
    int xA = (w >> 2) + 1 + ((rx < 2) ? -1 : 0);
    int yA = (l >> 2) + 1 + ((ry < 2) ? -1 : 0);
    int base = xA*10 + yA;
    float v[Cn];
    float mmax = -1e30f;
    #pragma unroll
    for (int c = 0; c < Cn; c++) {
        const float* mc = m_s + c*40 + base;
        float mu = wx0*(wy0*mc[0] + wy1*mc[1]) + wx1*(wy0*mc[10] + wy1*mc[11]);
        float vv = uw * __ldg(up + (size_t)c*Hn*Wn) + wgt * mu;
        v[c] = vv;
        mmax = fmaxf(mmax, vv);
    }
    float s = 0.f;
    #pragma unroll
    for (int c = 0; c < Cn; c++) { v[c] = __expf(v[c] - mmax); s += v[c]; }
    float inv = 1.f / s;
    int yq = l >> 2;
    #pragma unroll
    for (int c = 0; c < Cn; c++) {
        float r = v[c] * inv;
        r += __shfl_xor_sync(0xffffffffu, r, 1);
        r += __shfl_xor_sync(0xffffffffu, r, 2);
        if ((l & 3) == 0) part[(w*8 + yq)*Cn + c] = r;
    }
    __syncthreads();
    for (int idx = t; idx < 2*8*Cn; idx += 256) {
        int c = idx % Cn, rem = idx / Cn;
        int q = rem & 7, xc = rem >> 3;
        float ss = part[((xc*4+0)*8 + q)*Cn + c] + part[((xc*4+1)*8 + q)*Cn + c]
                 + part[((xc*4+2)*8 + q)*Cn + c] + part[((xc*4+3)*8 + q)*Cn + c];
        g_ppad[((size_t)(b*Cn + c)*PP + blockIdx.y*2 + xc + XOFF)*PP
               + blockIdx.x*8 + q + YOFF] = ss * 0.0625f;
    }
}

// ---------------------------------------------------------------------------
// 6) final, ONE row per thread (exact R11)
__global__ __launch_bounds__(256) void k_final(const float* __restrict__ unary,
                                               const float* __restrict__ weight,
                                               float* __restrict__ out) {
    __shared__ float m_s[Cn*40];
    int b = blockIdx.z;
    int t = threadIdx.x, w = t >> 5, l = t & 31;
    int lx0 = blockIdx.y*2 - 1, ly0 = blockIdx.x*8 - 1;
    for (int i = t; i < Cn*40; i += 256) {
        int c = i / 40, rem = i % 40;
        int xx = lx0 + rem/10; xx = max(0, min(HL-1, xx));
        int yy = ly0 + rem%10; yy = max(0, min(WL-1, yy));
        m_s[i] = g_msg[((b*Cn + c)*HL + xx)*WL + yy];
    }
    __syncthreads();
    int X = blockIdx.y*8 + w;
    int Y = blockIdx.x*32 + l;
    const float* up   = unary + ((size_t)(b*Cn)*Hn + X)*Wn + Y;
    float*       outp = out   + ((size_t)(b*Cn)*Hn + X)*Wn + Y;
    float wgt = weight[0], uw = 1.f - wgt;
    int rx = w & 3, ry = l & 3;
    float wx0 = c_wtab[rx], wx1 = 1.f - wx0;
    float wy0 = c_wtab[ry], wy1 = 1.f - wy0;
    int xA = (w >> 2) + 1 + ((rx < 2) ? -1 : 0);
    int yA = (l >> 2) + 1 + ((ry < 2) ? -1 : 0);
    int base = xA*10 + yA;
    float u[Cn];
    float m = -1e30f;
    #pragma unroll
    for (int c = 0; c < Cn; c++) {
        u[c] = __ldg(up + (size_t)c*Hn*Wn);
        m = fmaxf(m, u[c]);
    }
    float s = 0.f;
    #pragma unroll
    for (int c = 0; c < Cn; c++) s += __expf(u[c] - m);
    float lse = m + __logf(s);
    #pragma unroll
    for (int c = 0; c < Cn; c++) {
        const float* mc = m_s + c*40 + base;
        float mu = wx0*(wy0*mc[0] + wy1*mc[1]) + wx1*(wy0*mc[10] + wy1*mc[11]);
        outp[(size_t)c*Hn*Wn] = uw * (u[c] - lse) + wgt * mu;
    }
}

// ---------------------------------------------------------------------------
extern "C" void kernel_launch(void* const* d_in, const int* in_sizes, int n_in,
                              void* d_out, int out_size) {
    const float* unary      = (const float*)d_in[0];
    const float* img        = (const float*)d_in[1];
    const float* pos_sdims  = (const float*)d_in[2];
    const float* col_schan  = (const float*)d_in[3];
    const float* pos_compat = (const float*)d_in[4];
    const float* col_compat = (const float*)d_in[5];
    const float* weight     = (const float*)d_in[6];
    float* out = (float*)d_out;

    static int smem_set = 0;
    if (!smem_set) {
        cudaFuncSetAttribute(k_msg, cudaFuncAttributeMaxDynamicSharedMemorySize,
                             GK_SMEM_BYTES);
        smem_set = 1;
    }

    k_zero<<<(Bn*Cn*PLANE/4 + 255)/256, 256>>>();
    k_pool_img<<<(Bn*3*HL*WL + 255)/256, 256>>>(img, col_schan);
    k_init<<<dim3(16, 64, Bn), 256>>>(unary);
    for (int it = 0; it < 5; it++) {
        k_msg<<<dim3(8, 16, Bn), 224, GK_SMEM_BYTES>>>(pos_sdims, pos_compat, col_compat);
        if (it < 4)
            k_iter<<<dim3(16, 64, Bn), 256>>>(unary, weight);
        else
            k_final<<<dim3(16, 64, Bn), 256>>>(unary, weight, out);
    }
}